// round 5
// baseline (speedup 1.0000x reference)
#include <cuda_runtime.h>
#include <cuda_bf16.h>
#include <cstdint>

#define CIN  256
#define COUT 256
#define HDIM 64
#define WDIM 64
#define HW   4096
#define BATCH 8
#define WSZ  (256 * 256)
#define XYSZ ((size_t)BATCH * CIN * HW)

// Scratch (device globals; alloc-free rule).
__device__ __align__(128) float g_q[(size_t)BATCH * COUT * HW];
__device__ __align__(128) float g_k[(size_t)BATCH * COUT * HW];
__device__ __align__(128) float g_v[(size_t)BATCH * COUT * HW];
__device__ __align__(128) __nv_bfloat16 g_wh[3 * WSZ];
__device__ __align__(128) __nv_bfloat16 g_wl[3 * WSZ];
__device__ __align__(128) __nv_bfloat16 g_xh[XYSZ];
__device__ __align__(128) __nv_bfloat16 g_xl[XYSZ];
__device__ __align__(128) __nv_bfloat16 g_yh[XYSZ];
__device__ __align__(128) __nv_bfloat16 g_yl[XYSZ];

// ---------------------------------------------------------------------------
// helpers
// ---------------------------------------------------------------------------
// fp32 pair -> packed bf16x2 (lower 16 bits = a, upper = b)
__device__ __forceinline__ uint32_t f2bf2(float a, float b) {
    uint32_t r;
    asm("cvt.rn.satfinite.bf16x2.f32 %0, %1, %2;" : "=r"(r) : "f"(b), "f"(a));
    return r;
}

#define LDSM_X4(r0, r1, r2, r3, addr)                                           \
    asm volatile("ldmatrix.sync.aligned.m8n8.x4.shared.b16 {%0,%1,%2,%3}, [%4];"\
                 : "=r"(r0), "=r"(r1), "=r"(r2), "=r"(r3) : "r"(addr))

#define LDSM_X4_T(r0, r1, r2, r3, addr)                                         \
    asm volatile("ldmatrix.sync.aligned.m8n8.x4.trans.shared.b16 {%0,%1,%2,%3}, [%4];"\
                 : "=r"(r0), "=r"(r1), "=r"(r2), "=r"(r3) : "r"(addr))

#define MMA16816(d, a, b0, b1)                                                  \
    asm volatile("mma.sync.aligned.m16n8k16.row.col.f32.bf16.bf16.f32 "         \
        "{%0,%1,%2,%3}, {%4,%5,%6,%7}, {%8,%9}, {%0,%1,%2,%3};"                 \
        : "+f"((d)[0]), "+f"((d)[1]), "+f"((d)[2]), "+f"((d)[3])                \
        : "r"((a)[0]), "r"((a)[1]), "r"((a)[2]), "r"((a)[3]),                   \
          "r"(b0), "r"(b1))

#define CP16(dst, src)                                                          \
    asm volatile("cp.async.cg.shared.global [%0], [%1], 16;"                    \
                 :: "r"(dst), "l"(src) : "memory")
#define CP_COMMIT asm volatile("cp.async.commit_group;" ::: "memory")
#define CP_WAIT1  asm volatile("cp.async.wait_group 1;" ::: "memory")
#define CP_WAIT0  asm volatile("cp.async.wait_group 0;" ::: "memory")

// SMEM tile geometry (bf16 elems / bytes)
#define A_STRIDE 40         // 128x32 tile rows, padded (80 B/row)
#define B_STRIDE 136        // 32x128 tile rows, padded (272 B/row)
#define AH_SZ (128 * 80)    // 10240 B
#define BH_SZ (32 * 272)    //  8704 B
#define OFF_AL AH_SZ
#define OFF_BH (2 * AH_SZ)
#define OFF_BL (2 * AH_SZ + BH_SZ)
#define STAGE_SZ (2 * AH_SZ + 2 * BH_SZ)    // 37888 B
#define GEMM_SMEM (2 * STAGE_SZ)            // 75776 B

// ---------------------------------------------------------------------------
// Prep: split W matrices into bf16 hi/lo planes.
// grid (64, 3), 256 threads; each thread one float4.
// ---------------------------------------------------------------------------
__global__ __launch_bounds__(256)
void prep_w(const float* __restrict__ wq, const float* __restrict__ wk,
            const float* __restrict__ wv)
{
    const int z = blockIdx.y;
    const float* src = (z == 0) ? wq : (z == 1 ? wk : wv);
    const int i4 = blockIdx.x * 256 + threadIdx.x;     // float4 index
    const float4 a = *(const float4*)(src + i4 * 4);
    const uint32_t h01 = f2bf2(a.x, a.y);
    const uint32_t h23 = f2bf2(a.z, a.w);
    const float r0 = a.x - __int_as_float(h01 << 16);
    const float r1 = a.y - __int_as_float(h01 & 0xFFFF0000u);
    const float r2 = a.z - __int_as_float(h23 << 16);
    const float r3 = a.w - __int_as_float(h23 & 0xFFFF0000u);
    *(uint2*)((char*)(g_wh + z * WSZ) + (size_t)i4 * 8) = make_uint2(h01, h23);
    *(uint2*)((char*)(g_wl + z * WSZ) + (size_t)i4 * 8) =
        make_uint2(f2bf2(r0, r1), f2bf2(r2, r3));
}

// ---------------------------------------------------------------------------
// Prep: split x (z=0) and y (z=1) into bf16 hi/lo planes.
// grid (1024, 2), 256 threads; each thread 8 float4.
// Total: 1024*256*8 = 2,097,152 float4 = XYSZ/4 exactly.
// ---------------------------------------------------------------------------
__global__ __launch_bounds__(256)
void prep_xy(const float* __restrict__ x, const float* __restrict__ y)
{
    const int z = blockIdx.y;
    const float* src = z ? y : x;
    __nv_bfloat16* dh = z ? g_yh : g_xh;
    __nv_bfloat16* dl = z ? g_yl : g_xl;
    const size_t base = (size_t)blockIdx.x * 2048 + threadIdx.x;
    #pragma unroll
    for (int j = 0; j < 8; j++) {
        const size_t i4 = base + j * 256;
        const float4 a = *(const float4*)(src + i4 * 4);
        const uint32_t h01 = f2bf2(a.x, a.y);
        const uint32_t h23 = f2bf2(a.z, a.w);
        const float r0 = a.x - __int_as_float(h01 << 16);
        const float r1 = a.y - __int_as_float(h01 & 0xFFFF0000u);
        const float r2 = a.z - __int_as_float(h23 << 16);
        const float r3 = a.w - __int_as_float(h23 & 0xFFFF0000u);
        *(uint2*)((char*)dh + i4 * 8) = make_uint2(h01, h23);
        *(uint2*)((char*)dl + i4 * 8) = make_uint2(f2bf2(r0, r1), f2bf2(r2, r3));
    }
}

// ---------------------------------------------------------------------------
// GEMM: C[o,p] = sum_i W[o,i]*X[i,p] per batch, bf16 3-term hi/lo split,
// operands pre-converted. 128x128 tile, K-blocks 32, cp.async double buffer.
// blockIdx.z: 0 = q(wq,y), 1 = k(wk,x), 2 = v(wv,x).
// ---------------------------------------------------------------------------
__device__ __forceinline__ void issue_stage(
    uint32_t sbase, const __nv_bfloat16* __restrict__ wh,
    const __nv_bfloat16* __restrict__ wl, const __nv_bfloat16* __restrict__ xh,
    const __nv_bfloat16* __restrict__ xl, int m0, int k0, size_t xoff, int tid)
{
    #pragma unroll
    for (int i = 0; i < 2; i++) {
        const int c = tid + i * 256;
        const int r = c >> 2, ck = (c & 3) * 8;
        const uint32_t d = sbase + r * 80 + ck * 2;
        CP16(d, wh + (m0 + r) * 256 + k0 + ck);
        CP16(d + OFF_AL, wl + (m0 + r) * 256 + k0 + ck);
    }
    #pragma unroll
    for (int i = 0; i < 2; i++) {
        const int c = tid + i * 256;
        const int k = c >> 4, cn = (c & 15) * 8;
        const size_t so = xoff + (size_t)(k0 + k) * HW + cn;
        const uint32_t d = sbase + OFF_BH + k * 272 + cn * 2;
        CP16(d, xh + so);
        CP16(d + BH_SZ, xl + so);
    }
}

__global__ __launch_bounds__(256)
void qkv_gemm_mma(const float* dummy)
{
    extern __shared__ __align__(16) char smem[];
    const uint32_t sb = (uint32_t)__cvta_generic_to_shared(smem);

    const int z = blockIdx.z;
    const __nv_bfloat16* wh = g_wh + z * WSZ;
    const __nv_bfloat16* wl = g_wl + z * WSZ;
    const __nv_bfloat16* xh = (z == 0) ? g_yh : g_xh;
    const __nv_bfloat16* xl = (z == 0) ? g_yl : g_xl;
    float* C = (z == 0) ? g_q : (z == 1 ? g_k : g_v);

    const int n0  = blockIdx.x * 128;
    const int m0  = blockIdx.y * 128;
    const int b   = n0 >> 12;
    const int hw0 = n0 & 4095;
    const size_t xoff = (size_t)b * CIN * HW + hw0;
    float* Cb = C + (size_t)b * COUT * HW + hw0;

    const int tid  = threadIdx.x;
    const int lane = tid & 31;
    const int wid  = tid >> 5;
    const int wm   = (wid >> 1) * 32;
    const int wn   = (wid & 1) * 64;

    float acc[2][8][4];
    #pragma unroll
    for (int i = 0; i < 2; i++)
        #pragma unroll
        for (int j = 0; j < 8; j++)
            #pragma unroll
            for (int q = 0; q < 4; q++)
                acc[i][j][q] = 0.0f;

    issue_stage(sb, wh, wl, xh, xl, m0, 0, xoff, tid);
    CP_COMMIT;
    issue_stage(sb + STAGE_SZ, wh, wl, xh, xl, m0, 32, xoff, tid);
    CP_COMMIT;

    for (int it = 0; it < 8; it++) {
        if (it == 7) { CP_WAIT0; } else { CP_WAIT1; }
        __syncthreads();

        const uint32_t st = sb + (it & 1) * STAGE_SZ;
        #pragma unroll
        for (int ks = 0; ks < 2; ks++) {
            const int kb = ks * 16;
            uint32_t ah[2][4], al[2][4];
            #pragma unroll
            for (int mt = 0; mt < 2; mt++) {
                const uint32_t off =
                    (uint32_t)((wm + mt * 16 + (lane & 15)) * A_STRIDE + kb + (lane >> 4) * 8) * 2;
                LDSM_X4(ah[mt][0], ah[mt][1], ah[mt][2], ah[mt][3], st + off);
                LDSM_X4(al[mt][0], al[mt][1], al[mt][2], al[mt][3], st + OFF_AL + off);
            }
            #pragma unroll
            for (int ntp = 0; ntp < 4; ntp++) {
                const int nb = wn + ntp * 16;
                const uint32_t off =
                    (uint32_t)((kb + (lane & 15)) * B_STRIDE + nb + (lane >> 4) * 8) * 2;
                uint32_t bh[4], bl[4];
                LDSM_X4_T(bh[0], bh[1], bh[2], bh[3], st + OFF_BH + off);
                LDSM_X4_T(bl[0], bl[1], bl[2], bl[3], st + OFF_BL + off);
                #pragma unroll
                for (int mt = 0; mt < 2; mt++) {
                    #pragma unroll
                    for (int h2 = 0; h2 < 2; h2++) {
                        float* d = acc[mt][ntp * 2 + h2];
                        MMA16816(d, ah[mt], bh[h2 * 2], bh[h2 * 2 + 1]);
                        MMA16816(d, al[mt], bh[h2 * 2], bh[h2 * 2 + 1]);
                        MMA16816(d, ah[mt], bl[h2 * 2], bl[h2 * 2 + 1]);
                    }
                }
            }
        }
        __syncthreads();
        if (it < 6) {
            issue_stage(sb + (it & 1) * STAGE_SZ, wh, wl, xh, xl, m0, (it + 2) * 32, xoff, tid);
            CP_COMMIT;
        }
    }

    // ---- Epilogue ----
    #pragma unroll
    for (int mt = 0; mt < 2; mt++) {
        const int m = wm + mt * 16 + (lane >> 2);
        #pragma unroll
        for (int nt = 0; nt < 8; nt++) {
            const int n = wn + nt * 8 + (lane & 3) * 2;
            const float* d = acc[mt][nt];
            *(float2*)(Cb + (size_t)(m0 + m) * HW + n)     = make_float2(d[0], d[1]);
            *(float2*)(Cb + (size_t)(m0 + m + 8) * HW + n) = make_float2(d[2], d[3]);
        }
    }
}

// ---------------------------------------------------------------------------
// Window attention: SMEM-tiled, 4 px/thread, zero halo, no max-subtraction
// (logits bounded |l| << 88, denominator cannot fully underflow).
// ---------------------------------------------------------------------------
__global__ __launch_bounds__(256)
void attn_kernel2(const float* __restrict__ rel_h, const float* __restrict__ rel_w,
                  float* __restrict__ out)
{
    __shared__ float Ks[18][68];
    __shared__ float Vs[18][68];

    const int tid = threadIdx.x;
    const int h0  = blockIdx.x * 16;
    const int c   = blockIdx.y;
    const int b   = blockIdx.z;
    const size_t plane = ((size_t)b * COUT + c) * HW;
    const float* kp = g_k + plane;
    const float* vp = g_v + plane;

    for (int i = tid; i < 18 * 16; i += 256) {
        const int r = i >> 4, f4 = i & 15;
        const int gh = h0 - 1 + r;
        float4 kv = make_float4(0.f, 0.f, 0.f, 0.f);
        float4 vv = make_float4(0.f, 0.f, 0.f, 0.f);
        if ((unsigned)gh < (unsigned)HDIM) {
            kv = *(const float4*)(kp + gh * WDIM + f4 * 4);
            vv = *(const float4*)(vp + gh * WDIM + f4 * 4);
        }
        const int j = f4 * 4 + 1;
        Ks[r][j] = kv.x; Ks[r][j + 1] = kv.y; Ks[r][j + 2] = kv.z; Ks[r][j + 3] = kv.w;
        Vs[r][j] = vv.x; Vs[r][j + 1] = vv.y; Vs[r][j + 2] = vv.z; Vs[r][j + 3] = vv.w;
    }
    if (tid < 18) {
        Ks[tid][0] = 0.f; Ks[tid][65] = 0.f;
        Vs[tid][0] = 0.f; Vs[tid][65] = 0.f;
    }

    float b9[9];
    {
        const bool use_h = (c < 128);
        float bias[3];
        if (use_h) {
            bias[0] = rel_h[c * 3 + 0]; bias[1] = rel_h[c * 3 + 1]; bias[2] = rel_h[c * 3 + 2];
        } else {
            bias[0] = rel_w[(c - 128) * 3 + 0]; bias[1] = rel_w[(c - 128) * 3 + 1];
            bias[2] = rel_w[(c - 128) * 3 + 2];
        }
        #pragma unroll
        for (int dr = 0; dr < 3; dr++)
            #pragma unroll
            for (int dj = 0; dj < 3; dj++)
                b9[dr * 3 + dj] = use_h ? bias[dr] : bias[dj];
    }
    __syncthreads();

    const int lr = tid >> 4;
    const int w0 = (tid & 15) * 4;
    const int h  = h0 + lr;

    const float4 q4 = *(const float4*)(g_q + plane + h * WDIM + w0);
    const float q[4] = {q4.x, q4.y, q4.z, q4.w};

    float kk[3][6], vv[3][6];
    #pragma unroll
    for (int dr = 0; dr < 3; dr++) {
        const float* krow = &Ks[lr + dr][w0];
        const float* vrow = &Vs[lr + dr][w0];
        const float4 ka = *(const float4*)krow;
        const float2 kb = *(const float2*)(krow + 4);
        const float4 va = *(const float4*)vrow;
        const float2 vb = *(const float2*)(vrow + 4);
        kk[dr][0] = ka.x; kk[dr][1] = ka.y; kk[dr][2] = ka.z;
        kk[dr][3] = ka.w; kk[dr][4] = kb.x; kk[dr][5] = kb.y;
        vv[dr][0] = va.x; vv[dr][1] = va.y; vv[dr][2] = va.z;
        vv[dr][3] = va.w; vv[dr][4] = vb.x; vv[dr][5] = vb.y;
    }

    float res[4];
    #pragma unroll
    for (int p = 0; p < 4; p++) {
        float den = 0.f, num = 0.f;
        #pragma unroll
        for (int dr = 0; dr < 3; dr++)
            #pragma unroll
            for (int dj = 0; dj < 3; dj++) {
                const float e = __expf(q[p] * (kk[dr][p + dj] + b9[dr * 3 + dj]));
                den += e;
                num = fmaf(e, vv[dr][p + dj], num);
            }
        res[p] = __fdividef(num, den);
    }

    *(float4*)(out + plane + h * WDIM + w0) = make_float4(res[0], res[1], res[2], res[3]);
}

// ---------------------------------------------------------------------------
extern "C" void kernel_launch(void* const* d_in, const int* in_sizes, int n_in,
                              void* d_out, int out_size)
{
    const float* x     = (const float*)d_in[0];
    const float* y     = (const float*)d_in[1];
    const float* wq    = (const float*)d_in[2];
    const float* wk    = (const float*)d_in[3];
    const float* wv    = (const float*)d_in[4];
    const float* rel_h = (const float*)d_in[5];
    const float* rel_w = (const float*)d_in[6];
    float* out = (float*)d_out;

    cudaFuncSetAttribute(qkv_gemm_mma, cudaFuncAttributeMaxDynamicSharedMemorySize,
                         GEMM_SMEM);

    prep_w<<<dim3(64, 3), 256>>>(wq, wk, wv);
    prep_xy<<<dim3(1024, 2), 256>>>(x, y);

    dim3 ggrid(BATCH * HW / 128, COUT / 128, 3);   // (256, 2, 3)
    qkv_gemm_mma<<<ggrid, 256, GEMM_SMEM>>>(nullptr);

    dim3 agrid(HDIM / 16, COUT, BATCH);            // (4, 256, 8)
    attn_kernel2<<<agrid, 256>>>(rel_h, rel_w, out);
}